// round 1
// baseline (speedup 1.0000x reference)
#include <cuda_runtime.h>
#include <math.h>

#define BSZ  4
#define DIM  128
#define NPOS 16384
#define HH   128
#define WW   128
#define NHEADS 8
#define CH   16
#define HID  340
#define HID2 680

// ---------------- scratch (device globals; no allocation allowed) ----------
__device__ float g_bufA[BSZ*DIM*NPOS];
__device__ float g_bufB[BSZ*DIM*NPOS];
__device__ float g_bufC[BSZ*DIM*NPOS];
__device__ float g_bufD[BSZ*DIM*NPOS];
__device__ float g_kv1[BSZ*2*DIM*NPOS];
__device__ float g_kv2[BSZ*2*DIM*NPOS];
__device__ float g_t1[BSZ*HID2*NPOS];
__device__ float g_t2[BSZ*HID2*NPOS];
__device__ float g_attn[BSZ*NHEADS*CH*CH];
__device__ float g_gate_sum;

// ---------------- init ----------------
__global__ void init_kernel() {
    int idx = blockIdx.x * blockDim.x + threadIdx.x;
    if (idx < BSZ*NHEADS*CH*CH) g_attn[idx] = 0.f;
    if (idx == 0) g_gate_sum = 0.f;
}

// ---------------- LayerNorm over channel axis (channels_first) -------------
__global__ void ln_kernel(const float* __restrict__ in, float* __restrict__ out,
                          const float* __restrict__ w, const float* __restrict__ b) {
    int idx = blockIdx.x * blockDim.x + threadIdx.x;   // 0 .. BSZ*NPOS-1
    int bb  = idx / NPOS;
    int pos = idx % NPOS;
    const float* p = in  + (size_t)bb * DIM * NPOS + pos;
    float*       q = out + (size_t)bb * DIM * NPOS + pos;
    float s = 0.f;
    #pragma unroll 4
    for (int c = 0; c < DIM; c++) s += p[c * NPOS];
    float u = s * (1.f / DIM);
    float s2 = 0.f;
    #pragma unroll 4
    for (int c = 0; c < DIM; c++) { float d = p[c * NPOS] - u; s2 += d * d; }
    float var = s2 * (1.f / DIM);
    float inv = rsqrtf(var + 1e-6f);
    #pragma unroll 4
    for (int c = 0; c < DIM; c++) {
        q[c * NPOS] = w[c] * ((p[c * NPOS] - u) * inv) + b[c];
    }
}

// ---------------- 1x1 conv as tiled SGEMM -----------------
// out[b, co, n] = sum_ci W[co, ci] * X[b, ci, n]  (+bias)(relu)(+res)
// grid: (NPOS/128, ceil(Cout/128), BSZ), 256 threads
__global__ void gemm1x1(const float* __restrict__ Wm, const float* __restrict__ X,
                        float* __restrict__ Y, const float* __restrict__ bias,
                        const float* __restrict__ res,
                        int Cout, int K, int actmode) {
    const int BM = 128, BN = 128, BK = 8, TM = 8, TN = 8;
    int b = blockIdx.z;
    const float* Xb = X + (size_t)b * K * NPOS;
    float*       Yb = Y + (size_t)b * Cout * NPOS;
    const float* Rb = res ? res + (size_t)b * Cout * NPOS : nullptr;
    int m0 = blockIdx.y * BM, n0 = blockIdx.x * BN;

    __shared__ float As[BK][BM];
    __shared__ float Bs[BK][BN + 4];

    int tid = threadIdx.x;
    int tn = tid % 16, tm = tid / 16;
    int aM = tid % 128;
    int aK0 = tid / 128;            // 0 or 1
    int gRow = m0 + aM;
    int bK = tid / 32;              // 0..7
    int bN = (tid % 32) * 4;

    float acc[TM][TN];
    #pragma unroll
    for (int i = 0; i < TM; i++)
        #pragma unroll
        for (int j = 0; j < TN; j++) acc[i][j] = 0.f;

    for (int k0 = 0; k0 < K; k0 += BK) {
        #pragma unroll
        for (int kk = aK0; kk < BK; kk += 2) {
            int k = k0 + kk;
            As[kk][aM] = (gRow < Cout && k < K) ? Wm[gRow * K + k] : 0.f;
        }
        {
            int k = k0 + bK;
            float4 v = make_float4(0.f, 0.f, 0.f, 0.f);
            if (k < K) v = *reinterpret_cast<const float4*>(Xb + (size_t)k * NPOS + n0 + bN);
            *reinterpret_cast<float4*>(&Bs[bK][bN]) = v;
        }
        __syncthreads();
        #pragma unroll
        for (int k = 0; k < BK; ++k) {
            float ra[TM], rb[TN];
            #pragma unroll
            for (int i = 0; i < TM; i++) ra[i] = As[k][tm * TM + i];
            #pragma unroll
            for (int j = 0; j < TN; j++) rb[j] = Bs[k][tn * TN + j];
            #pragma unroll
            for (int i = 0; i < TM; i++)
                #pragma unroll
                for (int j = 0; j < TN; j++)
                    acc[i][j] = fmaf(ra[i], rb[j], acc[i][j]);
        }
        __syncthreads();
    }

    #pragma unroll
    for (int i = 0; i < TM; i++) {
        int row = m0 + tm * TM + i;
        if (row >= Cout) continue;
        float bv = bias ? bias[row] : 0.f;
        #pragma unroll
        for (int j = 0; j < TN; j++) {
            int col = n0 + tn * TN + j;
            float v = acc[i][j] + bv;
            if (actmode == 1) v = fmaxf(v, 0.f);
            if (Rb) v += Rb[(size_t)row * NPOS + col];
            Yb[(size_t)row * NPOS + col] = v;
        }
    }
}

// ---------------- depthwise 3x3, pad=1 ----------------
// actmode: 0 none, 1: out = tanh(acc) + in_center
__global__ void dw3x3(const float* __restrict__ in, const float* __restrict__ wgt,
                      float* __restrict__ out, int Cproc, int CtotIn, int CtotOut,
                      int cOffIn, int cOffOut, int actmode) {
    int idx = blockIdx.x * blockDim.x + threadIdx.x;
    int total = BSZ * Cproc * NPOS;
    if (idx >= total) return;
    int n = idx % NPOS;
    int c = (idx / NPOS) % Cproc;
    int b = idx / (NPOS * Cproc);
    int y = n / WW, x = n % WW;
    const float* pin = in + ((size_t)(b * CtotIn + cOffIn + c)) * NPOS;
    const float* wc = wgt + c * 9;
    float w0 = wc[0], w1 = wc[1], w2 = wc[2], w3 = wc[3], w4 = wc[4],
          w5 = wc[5], w6 = wc[6], w7 = wc[7], w8 = wc[8];
    float acc = 0.f;
    bool xm = (x > 0), xp = (x < WW - 1);
    if (y > 0) {
        const float* r = pin + (y - 1) * WW + x;
        if (xm) acc = fmaf(w0, r[-1], acc);
        acc = fmaf(w1, r[0], acc);
        if (xp) acc = fmaf(w2, r[1], acc);
    }
    {
        const float* r = pin + y * WW + x;
        if (xm) acc = fmaf(w3, r[-1], acc);
        acc = fmaf(w4, r[0], acc);
        if (xp) acc = fmaf(w5, r[1], acc);
    }
    if (y < HH - 1) {
        const float* r = pin + (y + 1) * WW + x;
        if (xm) acc = fmaf(w6, r[-1], acc);
        acc = fmaf(w7, r[0], acc);
        if (xp) acc = fmaf(w8, r[1], acc);
    }
    float o = acc;
    if (actmode == 1) o = tanhf(acc) + pin[y * WW + x];
    out[((size_t)(b * CtotOut + cOffOut + c)) * NPOS + n] = o;
}

// ---------------- L2-normalize rows of length NPOS ----------------
__global__ void rownorm(float* data, int rowsPerBatch, int batchChanStride) {
    int row = blockIdx.x;
    int b = row / rowsPerBatch, c = row % rowsPerBatch;
    float* p = data + ((size_t)b * batchChanStride + c) * NPOS;
    __shared__ float red[256];
    float s = 0.f;
    for (int i = threadIdx.x; i < NPOS; i += 256) { float v = p[i]; s += v * v; }
    red[threadIdx.x] = s;
    __syncthreads();
    for (int off = 128; off > 0; off >>= 1) {
        if (threadIdx.x < off) red[threadIdx.x] += red[threadIdx.x + off];
        __syncthreads();
    }
    float norm = sqrtf(red[0]);
    float scale = 1.f / fmaxf(norm, 1e-12f);
    for (int i = threadIdx.x; i < NPOS; i += 256) p[i] *= scale;
}

// ---------------- gate second conv (64->1) + sigmoid + global mean-sum -----
__global__ void gate2_kernel(const float* __restrict__ G, const float* __restrict__ g2w,
                             const float* __restrict__ g2b) {
    __shared__ float sw[64];
    __shared__ float red[256];
    int tid = threadIdx.x;
    if (tid < 64) sw[tid] = g2w[tid];
    __syncthreads();
    int pos = blockIdx.x * 256 + tid;          // 0..65535
    int b = pos / NPOS, n = pos % NPOS;
    const float* p = G + (size_t)b * 64 * NPOS + n;
    float acc = g2b[0];
    #pragma unroll
    for (int i = 0; i < 64; i++) acc = fmaf(sw[i], p[i * NPOS], acc);
    float g = 1.f / (1.f + expf(-acc));
    red[tid] = g;
    __syncthreads();
    for (int off = 128; off > 0; off >>= 1) {
        if (tid < off) red[tid] += red[tid + off];
        __syncthreads();
    }
    if (tid == 0) atomicAdd(&g_gate_sum, red[0]);
}

// ---------------- channel attention: attn[b,h,c,d] = sum_n q*k ----------------
// grid (nchunks=16, B*NHEADS), 256 threads = (c,d) pairs
__global__ void attn_kernel(const float* __restrict__ q, const float* __restrict__ k) {
    __shared__ float qs[CH][33];
    __shared__ float ks[CH][33];
    int bh = blockIdx.y;
    int b = bh / NHEADS, h = bh % NHEADS;
    int n0 = blockIdx.x * 1024;
    int tid = threadIdx.x;
    int c = tid / 16, d = tid % 16;
    const float* qb = q + ((size_t)b * DIM + h * CH) * NPOS;
    const float* kb = k + ((size_t)b * 2 * DIM + h * CH) * NPOS;
    float acc = 0.f;
    for (int s = 0; s < 1024; s += 32) {
        // load 16x32 tiles of q and k
        #pragma unroll
        for (int e = tid; e < 512; e += 256) {
            int row = e / 32, col = e % 32;
            qs[row][col] = qb[(size_t)row * NPOS + n0 + s + col];
            ks[row][col] = kb[(size_t)row * NPOS + n0 + s + col];
        }
        __syncthreads();
        #pragma unroll
        for (int j = 0; j < 32; j++)
            acc = fmaf(qs[c][j], ks[d][j], acc);
        __syncthreads();
    }
    atomicAdd(&g_attn[bh * 256 + tid], acc);
}

// ---------------- top-k mask + softmax (one thread per row) ----------------
__global__ void mask_softmax(const float* __restrict__ temp) {
    int r = threadIdx.x;           // 0..511
    if (r >= BSZ * NHEADS * CH) return;
    float mean = g_gate_sum * (1.f / (BSZ * NPOS));
    int dk = (int)(CH * mean);     // truncation toward zero like astype(int32)
    if (dk < 1) dk = 1;
    if (dk > CH) dk = CH;
    int bh = r / CH, c = r % CH;
    int h = bh % NHEADS;
    float t = temp[h];
    float a[CH];
    int base = bh * 256 + c * 16;
    #pragma unroll
    for (int d = 0; d < CH; d++) a[d] = g_attn[base + d] * t;
    // rank = #{i: a_i > a_j} + #{i: a_i == a_j && i < j}
    bool keep[CH];
    #pragma unroll
    for (int j = 0; j < CH; j++) {
        int rank = 0;
        #pragma unroll
        for (int i = 0; i < CH; i++) {
            if (a[i] > a[j] || (a[i] == a[j] && i < j)) rank++;
        }
        keep[j] = (rank < dk);
    }
    float m = -1e30f;
    #pragma unroll
    for (int j = 0; j < CH; j++) if (keep[j] && a[j] > m) m = a[j];
    float denom = 0.f;
    float e[CH];
    #pragma unroll
    for (int j = 0; j < CH; j++) {
        e[j] = keep[j] ? expf(a[j] - m) : 0.f;
        denom += e[j];
    }
    float inv = 1.f / denom;
    #pragma unroll
    for (int j = 0; j < CH; j++) g_attn[base + j] = e[j] * inv;
}

// ---------------- out = attn @ v ----------------
// grid (NPOS/256, B*NHEADS), 256 threads
__global__ void attnv_kernel(const float* __restrict__ kv, float* __restrict__ out) {
    __shared__ float as[256];
    int bh = blockIdx.y;
    int b = bh / NHEADS, h = bh % NHEADS;
    int tid = threadIdx.x;
    as[tid] = g_attn[bh * 256 + tid];
    __syncthreads();
    int n = blockIdx.x * 256 + tid;
    const float* vb = kv + ((size_t)b * 2 * DIM + DIM + h * CH) * NPOS + n;
    float vr[CH];
    #pragma unroll
    for (int d = 0; d < CH; d++) vr[d] = vb[(size_t)d * NPOS];
    float* ob = out + ((size_t)b * DIM + h * CH) * NPOS + n;
    #pragma unroll
    for (int c = 0; c < CH; c++) {
        float acc = 0.f;
        #pragma unroll
        for (int d = 0; d < CH; d++) acc = fmaf(as[c * 16 + d], vr[d], acc);
        ob[(size_t)c * NPOS] = acc;
    }
}

// ---------------- elementwise product of x1,x2 halves ----------------
// reads g_t1 [B,680,N] halves, writes compact g_t2 [B,340,N]
__global__ void prod_kernel() {
    int idx = blockIdx.x * blockDim.x + threadIdx.x;
    int total = BSZ * HID * NPOS;
    if (idx >= total) return;
    int n = idx % NPOS;
    int c = (idx / NPOS) % HID;
    int b = idx / (NPOS * HID);
    float v1 = g_t1[((size_t)(b * HID2 + c)) * NPOS + n];
    float v2 = g_t1[((size_t)(b * HID2 + HID + c)) * NPOS + n];
    g_t2[((size_t)(b * HID + c)) * NPOS + n] = v1 * v2;
}

// ============================================================================
extern "C" void kernel_launch(void* const* d_in, const int* in_sizes, int n_in,
                              void* d_out, int out_size) {
    const float* x      = (const float*)d_in[0];
    const float* y      = (const float*)d_in[1];
    const float* ln_w   = (const float*)d_in[2];
    const float* ln_b   = (const float*)d_in[3];
    const float* temp   = (const float*)d_in[4];
    const float* q_w    = (const float*)d_in[5];
    const float* qdw_w  = (const float*)d_in[6];
    const float* kv_w   = (const float*)d_in[7];
    const float* kvdw_w = (const float*)d_in[8];
    const float* po_w   = (const float*)d_in[9];
    const float* g1_w   = (const float*)d_in[10];
    const float* g1_b   = (const float*)d_in[11];
    const float* g2_w   = (const float*)d_in[12];
    const float* g2_b   = (const float*)d_in[13];
    const float* pin_w  = (const float*)d_in[14];
    const float* dw_w   = (const float*)d_in[15];
    const float* dw1_w  = (const float*)d_in[16];
    const float* dw2_w  = (const float*)d_in[17];
    const float* pout_w = (const float*)d_in[18];
    float* outp = (float*)d_out;

    float *A, *Bb, *C, *D, *KV1, *KV2, *T1, *T2;
    cudaGetSymbolAddress((void**)&A,   g_bufA);
    cudaGetSymbolAddress((void**)&Bb,  g_bufB);
    cudaGetSymbolAddress((void**)&C,   g_bufC);
    cudaGetSymbolAddress((void**)&D,   g_bufD);
    cudaGetSymbolAddress((void**)&KV1, g_kv1);
    cudaGetSymbolAddress((void**)&KV2, g_kv2);
    cudaGetSymbolAddress((void**)&T1,  g_t1);
    cudaGetSymbolAddress((void**)&T2,  g_t2);

    dim3 blk256(256);

    // 0. init attn accumulator + gate sum
    init_kernel<<<32, 256>>>();

    // 1. LayerNorms
    ln_kernel<<<BSZ * NPOS / 256, blk256>>>(x, A, ln_w, ln_b);
    ln_kernel<<<BSZ * NPOS / 256, blk256>>>(y, Bb, ln_w, ln_b);

    // 2. gate: g1 (128->64, bias, relu) -> D ; g2 dot + sigmoid + mean sum
    gemm1x1<<<dim3(NPOS / 128, 1, BSZ), blk256>>>(g1_w, A, D, g1_b, nullptr, 64, DIM, 1);
    gate2_kernel<<<BSZ * NPOS / 256, blk256>>>(D, g2_w, g2_b);

    // 3. q path: 1x1 conv then depthwise
    gemm1x1<<<dim3(NPOS / 128, 1, BSZ), blk256>>>(q_w, A, C, nullptr, nullptr, DIM, DIM, 0);
    dw3x3<<<(BSZ * DIM * NPOS) / 256, blk256>>>(C, qdw_w, D, DIM, DIM, DIM, 0, 0, 0);

    // 4. kv path
    gemm1x1<<<dim3(NPOS / 128, 2, BSZ), blk256>>>(kv_w, Bb, KV1, nullptr, nullptr, 2 * DIM, DIM, 0);
    dw3x3<<<(BSZ * 2 * DIM * NPOS) / 256, blk256>>>(KV1, kvdw_w, KV2, 2 * DIM, 2 * DIM, 2 * DIM, 0, 0, 0);

    // 5. L2-normalize q rows and k rows (over N)
    rownorm<<<BSZ * DIM, blk256>>>(D, DIM, DIM);            // q in D
    rownorm<<<BSZ * DIM, blk256>>>(KV2, DIM, 2 * DIM);      // k = first half of KV2

    // 6. attention scores, top-k mask + softmax
    attn_kernel<<<dim3(16, BSZ * NHEADS), blk256>>>(D, KV2);
    mask_softmax<<<1, 512>>>(temp);

    // 7. out = attn @ v  -> A
    attnv_kernel<<<dim3(NPOS / 256, BSZ * NHEADS), blk256>>>(KV2, A);

    // 8. x_new = x + conv1x1(out, po) -> Bb
    gemm1x1<<<dim3(NPOS / 128, 1, BSZ), blk256>>>(po_w, A, Bb, nullptr, x, DIM, DIM, 0);

    // 9. IEL: z = LN(x_new) -> A
    ln_kernel<<<BSZ * NPOS / 256, blk256>>>(Bb, A, ln_w, ln_b);

    // 10. pin 128->680 -> T1 ; dw depthwise 680 -> T2
    gemm1x1<<<dim3(NPOS / 128, (HID2 + 127) / 128, BSZ), blk256>>>(pin_w, A, T1, nullptr, nullptr, HID2, DIM, 0);
    dw3x3<<<(BSZ * HID2 * NPOS) / 256, blk256>>>(T1, dw_w, T2, HID2, HID2, HID2, 0, 0, 0);

    // 11. x1 = tanh(dw1(x1)) + x1 ; x2 = tanh(dw2(x2)) + x2  (T2 -> T1)
    dw3x3<<<(BSZ * HID * NPOS) / 256, blk256>>>(T2, dw1_w, T1, HID, HID2, HID2, 0, 0, 1);
    dw3x3<<<(BSZ * HID * NPOS) / 256, blk256>>>(T2, dw2_w, T1, HID, HID2, HID2, HID, HID, 1);

    // 12. prod = x1*x2 (compact [B,340,N]) -> T2
    prod_kernel<<<(BSZ * HID * NPOS) / 256, blk256>>>();

    // 13. out = conv1x1(prod, pout) + x_new -> d_out
    gemm1x1<<<dim3(NPOS / 128, 1, BSZ), blk256>>>(pout_w, T2, outp, nullptr, Bb, DIM, HID, 0);
}

// round 5
// speedup vs baseline: 1.9849x; 1.9849x over previous
#include <cuda_runtime.h>
#include <math.h>
#include <stdint.h>

#define BSZ  4
#define DIM  128
#define NPOS 16384
#define HH   128
#define WW   128
#define NHEADS 8
#define CH   16
#define HID  340
#define HID2 680

// ---------------- scratch (device globals; no allocation allowed) ----------
__device__ float g_bufA[BSZ*DIM*NPOS];
__device__ float g_bufB[BSZ*DIM*NPOS];
__device__ float g_bufC[BSZ*DIM*NPOS];
__device__ float g_bufD[BSZ*DIM*NPOS];
__device__ float g_kv1[BSZ*2*DIM*NPOS];
__device__ float g_kv2[BSZ*2*DIM*NPOS];
__device__ float g_t1[BSZ*HID2*NPOS];
__device__ float g_t2[BSZ*HID2*NPOS];
__device__ float g_attn[BSZ*NHEADS*CH*CH];
__device__ float g_qnorm[BSZ*DIM];
__device__ float g_knorm[BSZ*DIM];
__device__ float g_gate_sum;

// ---------------- init ----------------
__global__ void init_kernel() {
    int idx = blockIdx.x * blockDim.x + threadIdx.x;
    if (idx < BSZ*NHEADS*CH*CH) g_attn[idx] = 0.f;
    if (idx < BSZ*DIM) { g_qnorm[idx] = 0.f; g_knorm[idx] = 0.f; }
    if (idx == 0) g_gate_sum = 0.f;
}

// ---------------- LayerNorm over channel axis ----------------
__global__ void ln_kernel(const float* __restrict__ in, float* __restrict__ out,
                          const float* __restrict__ w, const float* __restrict__ b) {
    int idx = blockIdx.x * blockDim.x + threadIdx.x;   // 0 .. BSZ*NPOS-1
    int bb  = idx / NPOS;
    int pos = idx % NPOS;
    const float* p = in  + (size_t)bb * DIM * NPOS + pos;
    float*       q = out + (size_t)bb * DIM * NPOS + pos;
    float s = 0.f;
    #pragma unroll 4
    for (int c = 0; c < DIM; c++) s += p[c * NPOS];
    float u = s * (1.f / DIM);
    float s2 = 0.f;
    #pragma unroll 4
    for (int c = 0; c < DIM; c++) { float d = p[c * NPOS] - u; s2 += d * d; }
    float inv = rsqrtf(s2 * (1.f / DIM) + 1e-6f);
    #pragma unroll 4
    for (int c = 0; c < DIM; c++)
        q[c * NPOS] = w[c] * ((p[c * NPOS] - u) * inv) + b[c];
}

// ---------------- tf32 helpers ----------------
__device__ __forceinline__ float ftf32(float x) {
    uint32_t u;
    asm("cvt.rna.tf32.f32 %0, %1;" : "=r"(u) : "f"(x));
    return __uint_as_float(u);
}

// ---------------- 1x1 conv as tf32 tensor-core GEMM -----------------
// out[b,co,n] = sum_ci W[co,ci] * X[b,ci,n]  (+bias)(relu)(+res)
// grid (NPOS/128, ceil(Cout/128), BSZ), 256 threads, 8 warps each 64x32
__global__ __launch_bounds__(256, 2)
void gemm_tc(const float* __restrict__ Wm, const float* __restrict__ X,
             float* __restrict__ Y, const float* __restrict__ bias,
             const float* __restrict__ res, int Cout, int K, int actmode) {
    __shared__ float As[2][128][20];    // [buf][m][k], pad 20 -> conflict-free frags
    __shared__ float Bs[2][16][136];    // [buf][k][n], pad 136

    const int b = blockIdx.z;
    const float* Xb = X + (size_t)b * K * NPOS;
    float*       Yb = Y + (size_t)b * Cout * NPOS;
    const float* Rb = res ? res + (size_t)b * Cout * NPOS : nullptr;
    const int m0 = blockIdx.y * 128, n0 = blockIdx.x * 128;
    const int tid = threadIdx.x;
    const int lane = tid & 31;
    const int w = tid >> 5;
    const int wm = (w & 1) * 64, wn = (w >> 1) * 32;
    const int r = lane >> 2, cl = lane & 3;

    // global->smem mapping (2 float4 each for A and B)
    const int am  = tid >> 1;
    const int aq0 = (2*tid) & 3,       aq1 = (2*tid+1) & 3;
    const int bk0 = (2*tid) >> 5,      bq0 = (2*tid) & 31;
    const int bk1 = (2*tid+1) >> 5,    bq1 = (2*tid+1) & 31;

    float acc[4][4][4];
    #pragma unroll
    for (int i = 0; i < 4; i++)
        #pragma unroll
        for (int j = 0; j < 4; j++)
            #pragma unroll
            for (int e = 0; e < 4; e++) acc[i][j][e] = 0.f;

    float4 pA0, pA1, pB0, pB1;
    const int ntiles = (K + 15) / 16;

    auto loadT = [&](int t) {
        int k0 = t * 16;
        int mg = m0 + am;
        pA0 = make_float4(0.f,0.f,0.f,0.f); pA1 = pA0;
        if (mg < Cout) {
            if (k0 + aq0*4 + 4 <= K) pA0 = *(const float4*)(Wm + (size_t)mg*K + k0 + aq0*4);
            if (k0 + aq1*4 + 4 <= K) pA1 = *(const float4*)(Wm + (size_t)mg*K + k0 + aq1*4);
        }
        pB0 = make_float4(0.f,0.f,0.f,0.f); pB1 = pB0;
        if (k0 + bk0 < K) pB0 = *(const float4*)(Xb + (size_t)(k0+bk0)*NPOS + n0 + bq0*4);
        if (k0 + bk1 < K) pB1 = *(const float4*)(Xb + (size_t)(k0+bk1)*NPOS + n0 + bq1*4);
    };
    auto storeT = [&](int buf) {
        As[buf][am][aq0*4+0] = ftf32(pA0.x); As[buf][am][aq0*4+1] = ftf32(pA0.y);
        As[buf][am][aq0*4+2] = ftf32(pA0.z); As[buf][am][aq0*4+3] = ftf32(pA0.w);
        As[buf][am][aq1*4+0] = ftf32(pA1.x); As[buf][am][aq1*4+1] = ftf32(pA1.y);
        As[buf][am][aq1*4+2] = ftf32(pA1.z); As[buf][am][aq1*4+3] = ftf32(pA1.w);
        Bs[buf][bk0][bq0*4+0] = ftf32(pB0.x); Bs[buf][bk0][bq0*4+1] = ftf32(pB0.y);
        Bs[buf][bk0][bq0*4+2] = ftf32(pB0.z); Bs[buf][bk0][bq0*4+3] = ftf32(pB0.w);
        Bs[buf][bk1][bq1*4+0] = ftf32(pB1.x); Bs[buf][bk1][bq1*4+1] = ftf32(pB1.y);
        Bs[buf][bk1][bq1*4+2] = ftf32(pB1.z); Bs[buf][bk1][bq1*4+3] = ftf32(pB1.w);
    };
    auto compute = [&](int buf) {
        #pragma unroll
        for (int ks = 0; ks < 16; ks += 8) {
            float a[4][4], bf[4][2];
            #pragma unroll
            for (int tm = 0; tm < 4; tm++) {
                int row = wm + tm*16 + r;
                a[tm][0] = As[buf][row  ][ks+cl];
                a[tm][1] = As[buf][row+8][ks+cl];
                a[tm][2] = As[buf][row  ][ks+cl+4];
                a[tm][3] = As[buf][row+8][ks+cl+4];
            }
            #pragma unroll
            for (int tn = 0; tn < 4; tn++) {
                int col = wn + tn*8 + r;
                bf[tn][0] = Bs[buf][ks+cl  ][col];
                bf[tn][1] = Bs[buf][ks+cl+4][col];
            }
            #pragma unroll
            for (int tm = 0; tm < 4; tm++)
                #pragma unroll
                for (int tn = 0; tn < 4; tn++) {
                    asm volatile(
                      "mma.sync.aligned.m16n8k8.row.col.f32.tf32.tf32.f32 "
                      "{%0,%1,%2,%3}, {%4,%5,%6,%7}, {%8,%9}, {%0,%1,%2,%3};"
                      : "+f"(acc[tm][tn][0]), "+f"(acc[tm][tn][1]),
                        "+f"(acc[tm][tn][2]), "+f"(acc[tm][tn][3])
                      : "r"(__float_as_uint(a[tm][0])), "r"(__float_as_uint(a[tm][1])),
                        "r"(__float_as_uint(a[tm][2])), "r"(__float_as_uint(a[tm][3])),
                        "r"(__float_as_uint(bf[tn][0])), "r"(__float_as_uint(bf[tn][1])));
                }
        }
    };

    loadT(0); storeT(0); __syncthreads();
    for (int t = 0; t < ntiles; t++) {
        int buf = t & 1;
        bool more = (t + 1 < ntiles);
        if (more) loadT(t + 1);
        compute(buf);
        __syncthreads();
        if (more) { storeT(buf ^ 1); __syncthreads(); }
    }

    // epilogue
    #pragma unroll
    for (int tm = 0; tm < 4; tm++) {
        #pragma unroll
        for (int hh = 0; hh < 2; hh++) {
            int row = m0 + wm + tm*16 + r + hh*8;
            if (row >= Cout) continue;
            float bv = bias ? bias[row] : 0.f;
            #pragma unroll
            for (int tn = 0; tn < 4; tn++) {
                int col = n0 + wn + tn*8 + cl*2;
                float v0 = acc[tm][tn][hh*2+0] + bv;
                float v1 = acc[tm][tn][hh*2+1] + bv;
                if (actmode == 1) { v0 = fmaxf(v0, 0.f); v1 = fmaxf(v1, 0.f); }
                size_t off = (size_t)row * NPOS + col;
                if (Rb) { v0 += Rb[off]; v1 += Rb[off + 1]; }
                *(float2*)(Yb + off) = make_float2(v0, v1);
            }
        }
    }
}

// ---------------- depthwise 3x3 helper ----------------
__device__ __forceinline__ float conv9(const float* __restrict__ pin,
                                       const float* __restrict__ wc, int y, int x) {
    float acc = 0.f;
    bool xm = (x > 0), xp = (x < WW - 1);
    if (y > 0) {
        const float* rr = pin + (y - 1) * WW + x;
        if (xm) acc = fmaf(wc[0], rr[-1], acc);
        acc = fmaf(wc[1], rr[0], acc);
        if (xp) acc = fmaf(wc[2], rr[1], acc);
    }
    {
        const float* rr = pin + y * WW + x;
        if (xm) acc = fmaf(wc[3], rr[-1], acc);
        acc = fmaf(wc[4], rr[0], acc);
        if (xp) acc = fmaf(wc[5], rr[1], acc);
    }
    if (y < HH - 1) {
        const float* rr = pin + (y + 1) * WW + x;
        if (xm) acc = fmaf(wc[6], rr[-1], acc);
        acc = fmaf(wc[7], rr[0], acc);
        if (xp) acc = fmaf(wc[8], rr[1], acc);
    }
    return acc;
}

// depthwise 3x3 + optional per-(b,c) sum-of-squares accumulation (for q/k norms)
__global__ void dw3x3(const float* __restrict__ in, const float* __restrict__ wgt,
                      float* __restrict__ out, int Cproc, int CtotIn, int CtotOut,
                      int cOffIn, int cOffOut,
                      float* __restrict__ norms, int normC) {
    __shared__ float red[256];
    int idx = blockIdx.x * 256 + threadIdx.x;
    int n = idx % NPOS;
    int c = (idx / NPOS) % Cproc;
    int b = idx / (NPOS * Cproc);
    int y = n / WW, x = n % WW;
    const float* pin = in + ((size_t)(b * CtotIn + cOffIn + c)) * NPOS;
    float o = conv9(pin, wgt + c * 9, y, x);
    out[((size_t)(b * CtotOut + cOffOut + c)) * NPOS + n] = o;
    if (norms) {
        red[threadIdx.x] = (c < normC) ? o * o : 0.f;
        __syncthreads();
        for (int off = 128; off > 0; off >>= 1) {
            if (threadIdx.x < off) red[threadIdx.x] += red[threadIdx.x + off];
            __syncthreads();
        }
        if (threadIdx.x == 0 && c < normC) atomicAdd(&norms[b * normC + c], red[0]);
    }
}

// ---------------- fused dw1/dw2 + tanh-residual + product ----------------
// in: [B,680,N] ; out: compact [B,340,N]  out = (tanh(dw1(x1))+x1)*(tanh(dw2(x2))+x2)
__global__ void fused_dw12(const float* __restrict__ in,
                           const float* __restrict__ w1, const float* __restrict__ w2,
                           float* __restrict__ out) {
    int idx = blockIdx.x * 256 + threadIdx.x;
    int n = idx % NPOS;
    int c = (idx / NPOS) % HID;
    int b = idx / (NPOS * HID);
    int y = n / WW, x = n % WW;
    const float* p1 = in + ((size_t)(b * HID2 + c)) * NPOS;
    const float* p2 = p1 + (size_t)HID * NPOS;
    float o1 = tanhf(conv9(p1, w1 + c * 9, y, x)) + p1[n];
    float o2 = tanhf(conv9(p2, w2 + c * 9, y, x)) + p2[n];
    out[((size_t)(b * HID + c)) * NPOS + n] = o1 * o2;
}

// ---------------- gate second conv + sigmoid + global sum ----------------
__global__ void gate2_kernel(const float* __restrict__ G, const float* __restrict__ g2w,
                             const float* __restrict__ g2b) {
    __shared__ float sw[64];
    __shared__ float red[256];
    int tid = threadIdx.x;
    if (tid < 64) sw[tid] = g2w[tid];
    __syncthreads();
    int pos = blockIdx.x * 256 + tid;
    int b = pos / NPOS, n = pos % NPOS;
    const float* p = G + (size_t)b * 64 * NPOS + n;
    float acc = g2b[0];
    #pragma unroll
    for (int i = 0; i < 64; i++) acc = fmaf(sw[i], p[i * NPOS], acc);
    red[tid] = 1.f / (1.f + expf(-acc));
    __syncthreads();
    for (int off = 128; off > 0; off >>= 1) {
        if (tid < off) red[tid] += red[tid + off];
        __syncthreads();
    }
    if (tid == 0) atomicAdd(&g_gate_sum, red[0]);
}

// ---------------- channel attention raw dots: sum_n q*k (unnormalized) -----
__global__ void attn_kernel(const float* __restrict__ q, const float* __restrict__ k) {
    __shared__ float qs[CH][33];
    __shared__ float ks[CH][33];
    int bh = blockIdx.y;
    int b = bh / NHEADS, h = bh % NHEADS;
    int n0 = blockIdx.x * 1024;
    int tid = threadIdx.x;
    int c = tid / 16, d = tid % 16;
    const float* qb = q + ((size_t)b * DIM + h * CH) * NPOS;
    const float* kb = k + ((size_t)b * 2 * DIM + h * CH) * NPOS;
    float acc = 0.f;
    for (int s = 0; s < 1024; s += 32) {
        #pragma unroll
        for (int e = tid; e < 512; e += 256) {
            int row = e / 32, col = e % 32;
            qs[row][col] = qb[(size_t)row * NPOS + n0 + s + col];
            ks[row][col] = kb[(size_t)row * NPOS + n0 + s + col];
        }
        __syncthreads();
        #pragma unroll
        for (int j = 0; j < 32; j++)
            acc = fmaf(qs[c][j], ks[d][j], acc);
        __syncthreads();
    }
    atomicAdd(&g_attn[bh * 256 + tid], acc);
}

// ---------------- normalize + top-k mask + softmax (one thread per row) ----
__global__ void mask_softmax(const float* __restrict__ temp) {
    int rrow = threadIdx.x;
    if (rrow >= BSZ * NHEADS * CH) return;
    float mean = g_gate_sum * (1.f / (BSZ * NPOS));
    int dk = (int)(CH * mean);
    if (dk < 1) dk = 1;
    if (dk > CH) dk = CH;
    int bh = rrow / CH, c = rrow % CH;
    int b = bh / NHEADS, h = bh % NHEADS;
    float t = temp[h];
    float qn = fmaxf(sqrtf(g_qnorm[b * DIM + h * CH + c]), 1e-12f);
    float a[CH];
    int base = bh * 256 + c * 16;
    #pragma unroll
    for (int d = 0; d < CH; d++) {
        float kn = fmaxf(sqrtf(g_knorm[b * DIM + h * CH + d]), 1e-12f);
        a[d] = g_attn[base + d] * t / (qn * kn);
    }
    bool keep[CH];
    #pragma unroll
    for (int j = 0; j < CH; j++) {
        int rank = 0;
        #pragma unroll
        for (int i = 0; i < CH; i++)
            if (a[i] > a[j] || (a[i] == a[j] && i < j)) rank++;
        keep[j] = (rank < dk);
    }
    float m = -1e30f;
    #pragma unroll
    for (int j = 0; j < CH; j++) if (keep[j] && a[j] > m) m = a[j];
    float denom = 0.f;
    float e[CH];
    #pragma unroll
    for (int j = 0; j < CH; j++) {
        e[j] = keep[j] ? expf(a[j] - m) : 0.f;
        denom += e[j];
    }
    float inv = 1.f / denom;
    #pragma unroll
    for (int j = 0; j < CH; j++) g_attn[base + j] = e[j] * inv;
}

// ---------------- out = attn @ v ----------------
__global__ void attnv_kernel(const float* __restrict__ kv, float* __restrict__ out) {
    __shared__ float as[256];
    int bh = blockIdx.y;
    int b = bh / NHEADS, h = bh % NHEADS;
    int tid = threadIdx.x;
    as[tid] = g_attn[bh * 256 + tid];
    __syncthreads();
    int n = blockIdx.x * 256 + tid;
    const float* vb = kv + ((size_t)b * 2 * DIM + DIM + h * CH) * NPOS + n;
    float vr[CH];
    #pragma unroll
    for (int d = 0; d < CH; d++) vr[d] = vb[(size_t)d * NPOS];
    float* ob = out + ((size_t)b * DIM + h * CH) * NPOS + n;
    #pragma unroll
    for (int c = 0; c < CH; c++) {
        float acc = 0.f;
        #pragma unroll
        for (int d = 0; d < CH; d++) acc = fmaf(as[c * 16 + d], vr[d], acc);
        ob[(size_t)c * NPOS] = acc;
    }
}

// ============================================================================
extern "C" void kernel_launch(void* const* d_in, const int* in_sizes, int n_in,
                              void* d_out, int out_size) {
    const float* x      = (const float*)d_in[0];
    const float* y      = (const float*)d_in[1];
    const float* ln_w   = (const float*)d_in[2];
    const float* ln_b   = (const float*)d_in[3];
    const float* temp   = (const float*)d_in[4];
    const float* q_w    = (const float*)d_in[5];
    const float* qdw_w  = (const float*)d_in[6];
    const float* kv_w   = (const float*)d_in[7];
    const float* kvdw_w = (const float*)d_in[8];
    const float* po_w   = (const float*)d_in[9];
    const float* g1_w   = (const float*)d_in[10];
    const float* g1_b   = (const float*)d_in[11];
    const float* g2_w   = (const float*)d_in[12];
    const float* g2_b   = (const float*)d_in[13];
    const float* pin_w  = (const float*)d_in[14];
    const float* dw_w   = (const float*)d_in[15];
    const float* dw1_w  = (const float*)d_in[16];
    const float* dw2_w  = (const float*)d_in[17];
    const float* pout_w = (const float*)d_in[18];
    float* outp = (float*)d_out;

    float *A, *Bb, *C, *D, *KV1, *KV2, *T1, *T2, *Qn, *Kn;
    cudaGetSymbolAddress((void**)&A,   g_bufA);
    cudaGetSymbolAddress((void**)&Bb,  g_bufB);
    cudaGetSymbolAddress((void**)&C,   g_bufC);
    cudaGetSymbolAddress((void**)&D,   g_bufD);
    cudaGetSymbolAddress((void**)&KV1, g_kv1);
    cudaGetSymbolAddress((void**)&KV2, g_kv2);
    cudaGetSymbolAddress((void**)&T1,  g_t1);
    cudaGetSymbolAddress((void**)&T2,  g_t2);
    cudaGetSymbolAddress((void**)&Qn,  g_qnorm);
    cudaGetSymbolAddress((void**)&Kn,  g_knorm);

    dim3 blk256(256);

    init_kernel<<<32, 256>>>();

    // LayerNorms
    ln_kernel<<<BSZ * NPOS / 256, blk256>>>(x, A, ln_w, ln_b);
    ln_kernel<<<BSZ * NPOS / 256, blk256>>>(y, Bb, ln_w, ln_b);

    // gate: g1 (128->64, bias+relu) -> D ; g2 + sigmoid + mean-sum
    gemm_tc<<<dim3(NPOS / 128, 1, BSZ), blk256>>>(g1_w, A, D, g1_b, nullptr, 64, DIM, 1);
    gate2_kernel<<<BSZ * NPOS / 256, blk256>>>(D, g2_w, g2_b);

    // q path (dw also accumulates q row sum-of-squares)
    gemm_tc<<<dim3(NPOS / 128, 1, BSZ), blk256>>>(q_w, A, C, nullptr, nullptr, DIM, DIM, 0);
    dw3x3<<<(BSZ * DIM * NPOS) / 256, blk256>>>(C, qdw_w, D, DIM, DIM, DIM, 0, 0, Qn, DIM);

    // kv path (dw accumulates k-half sum-of-squares)
    gemm_tc<<<dim3(NPOS / 128, 2, BSZ), blk256>>>(kv_w, Bb, KV1, nullptr, nullptr, 2 * DIM, DIM, 0);
    dw3x3<<<(BSZ * 2 * DIM * NPOS) / 256, blk256>>>(KV1, kvdw_w, KV2, 2 * DIM, 2 * DIM, 2 * DIM, 0, 0, Kn, DIM);

    // attention scores (raw dots), then normalize+mask+softmax
    attn_kernel<<<dim3(16, BSZ * NHEADS), blk256>>>(D, KV2);
    mask_softmax<<<1, 512>>>(temp);

    // out = attn @ v -> A
    attnv_kernel<<<dim3(NPOS / 256, BSZ * NHEADS), blk256>>>(KV2, A);

    // x_new = x + conv1x1(out, po) -> Bb
    gemm_tc<<<dim3(NPOS / 128, 1, BSZ), blk256>>>(po_w, A, Bb, nullptr, x, DIM, DIM, 0);

    // IEL
    ln_kernel<<<BSZ * NPOS / 256, blk256>>>(Bb, A, ln_w, ln_b);
    gemm_tc<<<dim3(NPOS / 128, (HID2 + 127) / 128, BSZ), blk256>>>(pin_w, A, T1, nullptr, nullptr, HID2, DIM, 0);
    dw3x3<<<(BSZ * HID2 * NPOS) / 256, blk256>>>(T1, dw_w, T2, HID2, HID2, HID2, 0, 0, nullptr, 0);
    fused_dw12<<<(BSZ * HID * NPOS) / 256, blk256>>>(T2, dw1_w, dw2_w, T1);

    // out = conv1x1(prod, pout) + x_new -> d_out
    gemm_tc<<<dim3(NPOS / 128, 1, BSZ), blk256>>>(pout_w, T1, outp, nullptr, Bb, DIM, HID, 0);
}